// round 3
// baseline (speedup 1.0000x reference)
#include <cuda_runtime.h>

typedef unsigned long long u64;

// ---------------- device scratch ----------------
__device__ float g_Bmat[128 * 1024];     // [k'][ij]: k'<64 -> invSigma, k'>=64 -> -2*mu*invSigma
__device__ float g_Cc[1024];             // C[ij]
__device__ float g_KG[1024 * 128];       // [ij][c]: c<64 -> K, c>=64 -> v - K*mu
__device__ float g_W[1024 * 1024];       // weights
__device__ float g_part[8 * 1024 * 128]; // GEMM2 k-split partials
__device__ float g_denp[16 * 1024];      // den partials per GEMM1 n-block

// ---------------- packed f32x2 helpers ----------------
__device__ __forceinline__ u64 pack2(float lo, float hi) {
    u64 r; asm("mov.b64 %0,{%1,%2};" : "=l"(r) : "f"(lo), "f"(hi)); return r;
}
__device__ __forceinline__ void unpack2(u64 v, float& lo, float& hi) {
    asm("mov.b64 {%0,%1},%2;" : "=f"(lo), "=f"(hi) : "l"(v));
}
__device__ __forceinline__ void fma2(u64& c, u64 a, u64 b) {
    asm("fma.rn.f32x2 %0,%1,%2,%0;" : "+l"(c) : "l"(a), "l"(b));
}

// ---------------- kernel 1: per-(i,j) precompute, warp per ij ----------------
__global__ void precompute_ij(const float* __restrict__ Mu0, const float* __restrict__ Mu1,
                              const float* __restrict__ S0, const float* __restrict__ S1,
                              const float* __restrict__ tptr) {
    int gw = (blockIdx.x * blockDim.x + threadIdx.x) >> 5;
    int lane = threadIdx.x & 31;
    if (gw >= 1024) return;
    int ij = gw;
    int i = ij >> 5, j = ij & 31;
    float t = *tptr, u = 1.0f - t;
    float Csum = 0.0f;
    #pragma unroll
    for (int kk = 0; kk < 2; kk++) {
        int k = kk * 32 + lane;
        float s0 = S0[i * 64 + k], s1 = S1[j * 64 + k];
        float m0 = Mu0[i * 64 + k], m1 = Mu1[j * 64 + k];
        float Ds = sqrtf(4.0f * s0 * s1 + 0.0625f);
        float Cs = 0.5f * (Ds - 0.25f);
        float mu = u * m0 + t * m1;
        float Sig = u * u * s0 + t * t * s1 + 2.0f * t * u * (Cs + 0.125f);
        float St = t * s1 + u * Cs - (u * s0 + t * Cs) - 0.25f * t;
        float invS = 1.0f / Sig;
        float Kv = St * invS;
        float v = m1 - m0;
        g_Bmat[k * 1024 + ij] = invS;
        g_Bmat[(64 + k) * 1024 + ij] = -2.0f * mu * invS;
        g_KG[ij * 128 + k] = Kv;
        g_KG[ij * 128 + 64 + k] = v - Kv * mu;
        Csum += mu * mu * invS + logf(Sig);
    }
    #pragma unroll
    for (int o = 16; o > 0; o >>= 1) Csum += __shfl_xor_sync(0xffffffffu, Csum, o);
    if (lane == 0) g_Cc[ij] = Csum;
}

// ================= GEMM core macro-ish pieces =================
// Block: BM=128, BN=64, BK=16, 128 threads, thread tile 8m x 8n,
// acc packed f32x2 along M (4 m-pairs x 8 n).

// ---------------- GEMM1: q = Xext @ Bmat, W epilogue ----------------
__global__ __launch_bounds__(128) void gemm1_kernel(const float* __restrict__ X,
                                                    const float* __restrict__ Lam) {
    __shared__ float As[2][16][128];  // [buf][k][m] 16 KB
    __shared__ float Bs[2][16][64];   // [buf][k][n]  8 KB

    const int tid = threadIdx.x;
    const int tx = tid & 7, ty = tid >> 3;          // 8 x 16 thread grid
    const int m0 = blockIdx.x * 128, n0 = blockIdx.y * 64;

    const int rB = tid >> 3;          // B stage: k-row 0..15
    const int cB = (tid & 7) * 8;     // B stage: n-col

    u64 acc[4][8];
    #pragma unroll
    for (int i = 0; i < 4; i++)
        #pragma unroll
        for (int j = 0; j < 8; j++) acc[i][j] = 0ULL;

    // ---- stage chunk 0 ----
    {
        #pragma unroll
        for (int seg = 0; seg < 4; seg++) {
            float4 v = *(const float4*)&X[(m0 + tid) * 64 + seg * 4];  // chunk0 cols 0..15, squared
            v.x *= v.x; v.y *= v.y; v.z *= v.z; v.w *= v.w;
            As[0][seg * 4 + 0][tid] = v.x; As[0][seg * 4 + 1][tid] = v.y;
            As[0][seg * 4 + 2][tid] = v.z; As[0][seg * 4 + 3][tid] = v.w;
        }
        *(float4*)&Bs[0][rB][cB]     = *(const float4*)&g_Bmat[rB * 1024 + n0 + cB];
        *(float4*)&Bs[0][rB][cB + 4] = *(const float4*)&g_Bmat[rB * 1024 + n0 + cB + 4];
    }
    __syncthreads();

    #pragma unroll 1
    for (int c = 0; c < 8; c++) {
        const int p = c & 1;
        float4 va[4]; float4 vb0, vb1;
        if (c < 7) {
            int cc = c + 1;
            int colbase = (cc & 3) * 16;
            #pragma unroll
            for (int seg = 0; seg < 4; seg++)
                va[seg] = *(const float4*)&X[(m0 + tid) * 64 + colbase + seg * 4];
            if (cc < 4) {
                #pragma unroll
                for (int seg = 0; seg < 4; seg++) {
                    va[seg].x *= va[seg].x; va[seg].y *= va[seg].y;
                    va[seg].z *= va[seg].z; va[seg].w *= va[seg].w;
                }
            }
            vb0 = *(const float4*)&g_Bmat[(cc * 16 + rB) * 1024 + n0 + cB];
            vb1 = *(const float4*)&g_Bmat[(cc * 16 + rB) * 1024 + n0 + cB + 4];
        }
        #pragma unroll
        for (int k = 0; k < 16; k++) {
            ulonglong2 a01 = *(const ulonglong2*)&As[p][k][ty * 8];      // {m0,m1},{m2,m3}
            ulonglong2 a23 = *(const ulonglong2*)&As[p][k][ty * 8 + 4];  // {m4,m5},{m6,m7}
            float4 b0 = *(const float4*)&Bs[p][k][tx * 8];
            float4 b1 = *(const float4*)&Bs[p][k][tx * 8 + 4];
            u64 bb[8] = {pack2(b0.x, b0.x), pack2(b0.y, b0.y), pack2(b0.z, b0.z), pack2(b0.w, b0.w),
                         pack2(b1.x, b1.x), pack2(b1.y, b1.y), pack2(b1.z, b1.z), pack2(b1.w, b1.w)};
            u64 am[4] = {a01.x, a01.y, a23.x, a23.y};
            #pragma unroll
            for (int i = 0; i < 4; i++)
                #pragma unroll
                for (int j = 0; j < 8; j++)
                    fma2(acc[i][j], am[i], bb[j]);
        }
        if (c < 7) {
            #pragma unroll
            for (int seg = 0; seg < 4; seg++) {
                As[p ^ 1][seg * 4 + 0][tid] = va[seg].x; As[p ^ 1][seg * 4 + 1][tid] = va[seg].y;
                As[p ^ 1][seg * 4 + 2][tid] = va[seg].z; As[p ^ 1][seg * 4 + 3][tid] = va[seg].w;
            }
            *(float4*)&Bs[p ^ 1][rB][cB]     = vb0;
            *(float4*)&Bs[p ^ 1][rB][cB + 4] = vb1;
            __syncthreads();
        }
    }

    // ---- epilogue: W = exp(clip(-0.5*(q+C)))*Lam ; per-row den partials ----
    float cc[8], ll[8];
    *(float4*)&cc[0] = *(const float4*)&g_Cc[n0 + tx * 8];
    *(float4*)&cc[4] = *(const float4*)&g_Cc[n0 + tx * 8 + 4];
    *(float4*)&ll[0] = *(const float4*)&Lam[n0 + tx * 8];
    *(float4*)&ll[4] = *(const float4*)&Lam[n0 + tx * 8 + 4];

    #pragma unroll
    for (int mp = 0; mp < 4; mp++) {
        float wlo[8], whi[8];
        #pragma unroll
        for (int j = 0; j < 8; j++) {
            float qlo, qhi;
            unpack2(acc[mp][j], qlo, qhi);
            wlo[j] = __expf(fminf(fmaxf(-0.5f * (qlo + cc[j]), -50.0f), 50.0f)) * ll[j];
            whi[j] = __expf(fminf(fmaxf(-0.5f * (qhi + cc[j]), -50.0f), 50.0f)) * ll[j];
        }
        int mlo = m0 + ty * 8 + 2 * mp;
        *(float4*)&g_W[mlo * 1024 + n0 + tx * 8]           = *(float4*)&wlo[0];
        *(float4*)&g_W[mlo * 1024 + n0 + tx * 8 + 4]       = *(float4*)&wlo[4];
        *(float4*)&g_W[(mlo + 1) * 1024 + n0 + tx * 8]     = *(float4*)&whi[0];
        *(float4*)&g_W[(mlo + 1) * 1024 + n0 + tx * 8 + 4] = *(float4*)&whi[4];
        float rlo = ((wlo[0] + wlo[1]) + (wlo[2] + wlo[3])) + ((wlo[4] + wlo[5]) + (wlo[6] + wlo[7]));
        float rhi = ((whi[0] + whi[1]) + (whi[2] + whi[3])) + ((whi[4] + whi[5]) + (whi[6] + whi[7]));
        #pragma unroll
        for (int o = 1; o < 8; o <<= 1) {
            rlo += __shfl_xor_sync(0xffffffffu, rlo, o);
            rhi += __shfl_xor_sync(0xffffffffu, rhi, o);
        }
        if (tx == 0) {
            g_denp[blockIdx.y * 1024 + mlo]     = rlo;
            g_denp[blockIdx.y * 1024 + mlo + 1] = rhi;
        }
    }
}

// ---------------- GEMM2: part = W @ KG, k-split 8 ----------------
__global__ __launch_bounds__(128) void gemm2_kernel() {
    __shared__ float As[2][16][128];
    __shared__ float Bs[2][16][64];

    const int tid = threadIdx.x;
    const int tx = tid & 7, ty = tid >> 3;
    const int m0 = blockIdx.x * 128, n0 = blockIdx.y * 64;
    const int k0 = blockIdx.z * 128;

    const int rB = tid >> 3;
    const int cB = (tid & 7) * 8;

    u64 acc[4][8];
    #pragma unroll
    for (int i = 0; i < 4; i++)
        #pragma unroll
        for (int j = 0; j < 8; j++) acc[i][j] = 0ULL;

    {
        #pragma unroll
        for (int seg = 0; seg < 4; seg++) {
            float4 v = *(const float4*)&g_W[(m0 + tid) * 1024 + k0 + seg * 4];
            As[0][seg * 4 + 0][tid] = v.x; As[0][seg * 4 + 1][tid] = v.y;
            As[0][seg * 4 + 2][tid] = v.z; As[0][seg * 4 + 3][tid] = v.w;
        }
        *(float4*)&Bs[0][rB][cB]     = *(const float4*)&g_KG[(k0 + rB) * 128 + n0 + cB];
        *(float4*)&Bs[0][rB][cB + 4] = *(const float4*)&g_KG[(k0 + rB) * 128 + n0 + cB + 4];
    }
    __syncthreads();

    #pragma unroll 1
    for (int c = 0; c < 8; c++) {
        const int p = c & 1;
        float4 va[4]; float4 vb0, vb1;
        if (c < 7) {
            int cc = c + 1;
            #pragma unroll
            for (int seg = 0; seg < 4; seg++)
                va[seg] = *(const float4*)&g_W[(m0 + tid) * 1024 + k0 + cc * 16 + seg * 4];
            vb0 = *(const float4*)&g_KG[(k0 + cc * 16 + rB) * 128 + n0 + cB];
            vb1 = *(const float4*)&g_KG[(k0 + cc * 16 + rB) * 128 + n0 + cB + 4];
        }
        #pragma unroll
        for (int k = 0; k < 16; k++) {
            ulonglong2 a01 = *(const ulonglong2*)&As[p][k][ty * 8];
            ulonglong2 a23 = *(const ulonglong2*)&As[p][k][ty * 8 + 4];
            float4 b0 = *(const float4*)&Bs[p][k][tx * 8];
            float4 b1 = *(const float4*)&Bs[p][k][tx * 8 + 4];
            u64 bb[8] = {pack2(b0.x, b0.x), pack2(b0.y, b0.y), pack2(b0.z, b0.z), pack2(b0.w, b0.w),
                         pack2(b1.x, b1.x), pack2(b1.y, b1.y), pack2(b1.z, b1.z), pack2(b1.w, b1.w)};
            u64 am[4] = {a01.x, a01.y, a23.x, a23.y};
            #pragma unroll
            for (int i = 0; i < 4; i++)
                #pragma unroll
                for (int j = 0; j < 8; j++)
                    fma2(acc[i][j], am[i], bb[j]);
        }
        if (c < 7) {
            #pragma unroll
            for (int seg = 0; seg < 4; seg++) {
                As[p ^ 1][seg * 4 + 0][tid] = va[seg].x; As[p ^ 1][seg * 4 + 1][tid] = va[seg].y;
                As[p ^ 1][seg * 4 + 2][tid] = va[seg].z; As[p ^ 1][seg * 4 + 3][tid] = va[seg].w;
            }
            *(float4*)&Bs[p ^ 1][rB][cB]     = vb0;
            *(float4*)&Bs[p ^ 1][rB][cB + 4] = vb1;
            __syncthreads();
        }
    }

    const int s = blockIdx.z;
    #pragma unroll
    for (int mp = 0; mp < 4; mp++) {
        float vlo[8], vhi[8];
        #pragma unroll
        for (int j = 0; j < 8; j++) unpack2(acc[mp][j], vlo[j], vhi[j]);
        int mlo = m0 + ty * 8 + 2 * mp;
        *(float4*)&g_part[(s * 1024 + mlo) * 128 + n0 + tx * 8]           = *(float4*)&vlo[0];
        *(float4*)&g_part[(s * 1024 + mlo) * 128 + n0 + tx * 8 + 4]       = *(float4*)&vlo[4];
        *(float4*)&g_part[(s * 1024 + mlo + 1) * 128 + n0 + tx * 8]       = *(float4*)&vhi[0];
        *(float4*)&g_part[(s * 1024 + mlo + 1) * 128 + n0 + tx * 8 + 4]   = *(float4*)&vhi[4];
    }
}

// ---------------- final: block per batch row ----------------
__global__ void final_kernel(const float* __restrict__ X, float* __restrict__ out) {
    __shared__ float s_den;
    int b = blockIdx.x, k = threadIdx.x;  // 64 threads
    float A = 0.0f, Bv = 0.0f;
    #pragma unroll
    for (int s = 0; s < 8; s++) {
        A  += g_part[(s * 1024 + b) * 128 + k];
        Bv += g_part[(s * 1024 + b) * 128 + 64 + k];
    }
    if (k < 32) {
        float d = (k < 16) ? g_denp[k * 1024 + b] : 0.0f;
        #pragma unroll
        for (int o = 8; o > 0; o >>= 1) d += __shfl_xor_sync(0xffffffffu, d, o);
        if (k == 0) s_den = d;
    }
    __syncthreads();
    out[b * 64 + k] = (X[b * 64 + k] * A + Bv) / s_den;
}

// ---------------- launch ----------------
extern "C" void kernel_launch(void* const* d_in, const int* in_sizes, int n_in,
                              void* d_out, int out_size) {
    const float* X   = (const float*)d_in[0];
    const float* Mu0 = (const float*)d_in[1];
    const float* Mu1 = (const float*)d_in[2];
    const float* S0  = (const float*)d_in[3];
    const float* S1  = (const float*)d_in[4];
    const float* Lam = (const float*)d_in[5];
    const float* t   = (const float*)d_in[6];
    float* out = (float*)d_out;

    precompute_ij<<<128, 256>>>(Mu0, Mu1, S0, S1, t);
    gemm1_kernel<<<dim3(8, 16), 128>>>(X, Lam);
    gemm2_kernel<<<dim3(8, 2, 8), 128>>>();
    final_kernel<<<1024, 64>>>(X, out);
}